// round 7
// baseline (speedup 1.0000x reference)
#include <cuda_runtime.h>
#include <cuda_fp16.h>
#include <cstdint>

// ============================================================================
// MoE (uniform-routing Gemma4 experts):
//   out = sum_e gelu_tanh(X @ Gw[e]^T) * (X @ Uw[e]^T) @ Dw[e]^T * (1/E)
// T=8192 H=2048 F=1024 E=8.
// Portable sm_103 path: mma.sync.m16n8k16 + cp.async + ldmatrix.
// R7: 64x64 warp tiles (MMA:LDSM 4.0), 1 CTA/SM, 8 warps.
// ============================================================================

namespace moe {

constexpr int T = 8192, H = 2048, F = 1024, E = 8;

__device__ __half g_Xh[(size_t)T * H];
__device__ __half g_Gh[(size_t)E * F * H];
__device__ __half g_Uh[(size_t)E * F * H];
__device__ __half g_Dh[(size_t)E * H * F];
__device__ __half g_Ah[(size_t)E * T * F];

#define DEVI __device__ __forceinline__

DEVI uint32_t smem_u32(const void* p) {
    uint32_t a;
    asm("{ .reg .u64 t; cvta.to.shared.u64 t, %1; cvt.u32.u64 %0, t; }"
        : "=r"(a) : "l"(p));
    return a;
}

DEVI void cp16(uint32_t dst, const void* src) {
    asm volatile("cp.async.cg.shared.global [%0], [%1], 16;"
                 :: "r"(dst), "l"(src) : "memory");
}
DEVI void cp_commit() { asm volatile("cp.async.commit_group;" ::: "memory"); }
template <int N>
DEVI void cp_wait() { asm volatile("cp.async.wait_group %0;" :: "n"(N) : "memory"); }

DEVI void ldm_x4(uint32_t* r, uint32_t addr) {
    asm volatile("ldmatrix.sync.aligned.m8n8.x4.shared.b16 {%0,%1,%2,%3}, [%4];"
                 : "=r"(r[0]), "=r"(r[1]), "=r"(r[2]), "=r"(r[3]) : "r"(addr));
}

DEVI void mma16816(float* d, const uint32_t* a, const uint32_t* b) {
    asm volatile(
        "mma.sync.aligned.m16n8k16.row.col.f32.f16.f16.f32 "
        "{%0,%1,%2,%3}, {%4,%5,%6,%7}, {%8,%9}, {%0,%1,%2,%3};"
        : "+f"(d[0]), "+f"(d[1]), "+f"(d[2]), "+f"(d[3])
        : "r"(a[0]), "r"(a[1]), "r"(a[2]), "r"(a[3]), "r"(b[0]), "r"(b[1]));
}

DEVI float gelu_tanh(float x) {
    return 0.5f * x * (1.0f + tanhf(0.7978845608028654f * x * (1.0f + 0.044715f * x * x)));
}

// ---- tiling constants ----
constexpr int BM = 128;        // M tile
constexpr int BK = 32;         // K chunk (halves)
constexpr int ST = 4;          // pipeline stages
constexpr int LDS = 40;        // smem row stride (halves); 80B rows: conflict-free ldmatrix
constexpr int ROWB = LDS * 2;  // 80

DEVI uint32_t a_ldm_off(int lane, int m_row, int ks) {
    return ((uint32_t)(m_row + (lane & 15)) * LDS + ks * 16 + ((lane >> 4) << 3)) * 2;
}
DEVI uint32_t b_ldm_off(int lane, int n_row, int ks) {
    return ((uint32_t)(n_row + ((lane >> 4) << 3) + (lane & 7)) * LDS +
            ks * 16 + (((lane >> 3) & 1) << 3)) * 2;
}

// ---------------------------------------------------------------------------
// Kernel 1: gate & up GEMMs fused + gelu*mul -> g_Ah (fp16)
//   grid (T/128, F/128, E), 8 warps = 2M x 4N, warp tile 64x32 per GEMM (x2)
// ---------------------------------------------------------------------------
constexpr int BN1 = 128;
constexpr uint32_t K1_SA = 0;
constexpr uint32_t K1_SG = BM * ROWB;               // 10240
constexpr uint32_t K1_SU = K1_SG + BN1 * ROWB;      // 20480
constexpr uint32_t K1_STAGE = K1_SU + BN1 * ROWB;   // 30720
constexpr uint32_t K1_SMEM = ST * K1_STAGE;         // 122880

__global__ void __launch_bounds__(256, 1)
gate_up_kernel() {
    extern __shared__ __align__(16) char smem[];
    const uint32_t sb = smem_u32(smem);
    const int tid = threadIdx.x, lane = tid & 31, wid = tid >> 5;
    const int m0 = blockIdx.x * BM;
    const int n0 = blockIdx.y * BN1;
    const int e  = blockIdx.z;
    const int m0w = (wid & 1) * 64;    // 2 warps over M (64 each)
    const int n0w = (wid >> 1) * 32;   // 4 warps over N (32 each)

    const __half* gA = g_Xh + (size_t)m0 * H;
    const __half* gG = g_Gh + ((size_t)e * F + n0) * H;
    const __half* gU = g_Uh + ((size_t)e * F + n0) * H;

    const int r  = tid >> 2;       // 0..63
    const int c8 = (tid & 3) * 8;  // halves

    auto load_stage = [&](int s, int kt) {
        const uint32_t base = sb + (uint32_t)s * K1_STAGE;
        const int k0 = kt * BK;
        cp16(base + K1_SA + (uint32_t)r * ROWB + (tid & 3) * 16,
             gA + (size_t)r * H + k0 + c8);
        cp16(base + K1_SA + (uint32_t)(r + 64) * ROWB + (tid & 3) * 16,
             gA + (size_t)(r + 64) * H + k0 + c8);
        cp16(base + K1_SG + (uint32_t)r * ROWB + (tid & 3) * 16,
             gG + (size_t)r * H + k0 + c8);
        cp16(base + K1_SG + (uint32_t)(r + 64) * ROWB + (tid & 3) * 16,
             gG + (size_t)(r + 64) * H + k0 + c8);
        cp16(base + K1_SU + (uint32_t)r * ROWB + (tid & 3) * 16,
             gU + (size_t)r * H + k0 + c8);
        cp16(base + K1_SU + (uint32_t)(r + 64) * ROWB + (tid & 3) * 16,
             gU + (size_t)(r + 64) * H + k0 + c8);
    };

    constexpr int NK = H / BK;  // 64
    for (int s = 0; s < ST - 1; s++) { load_stage(s, s); cp_commit(); }

    float accG[4][4][4], accU[4][4][4];  // [m16 tile][n8 tile][frag]
#pragma unroll
    for (int mt = 0; mt < 4; mt++)
#pragma unroll
        for (int nt = 0; nt < 4; nt++)
#pragma unroll
            for (int q = 0; q < 4; q++) { accG[mt][nt][q] = 0.f; accU[mt][nt][q] = 0.f; }

#pragma unroll 1
    for (int kt = 0; kt < NK; kt++) {
        cp_wait<ST - 2>();
        __syncthreads();
        if (kt + ST - 1 < NK) { load_stage((kt + ST - 1) & (ST - 1), kt + ST - 1); cp_commit(); }

        const uint32_t stg = sb + (uint32_t)(kt & (ST - 1)) * K1_STAGE;
#pragma unroll
        for (int ks = 0; ks < 2; ks++) {
            uint32_t a[4][4], bg[2][4], bu[2][4];
#pragma unroll
            for (int mt = 0; mt < 4; mt++)
                ldm_x4(a[mt], stg + K1_SA + a_ldm_off(lane, m0w + mt * 16, ks));
#pragma unroll
            for (int nt2 = 0; nt2 < 2; nt2++) {
                ldm_x4(bg[nt2], stg + K1_SG + b_ldm_off(lane, n0w + nt2 * 16, ks));
                ldm_x4(bu[nt2], stg + K1_SU + b_ldm_off(lane, n0w + nt2 * 16, ks));
            }
#pragma unroll
            for (int mt = 0; mt < 4; mt++)
#pragma unroll
                for (int nt = 0; nt < 4; nt++) {
                    mma16816(accG[mt][nt], a[mt], &bg[nt >> 1][(nt & 1) * 2]);
                    mma16816(accU[mt][nt], a[mt], &bu[nt >> 1][(nt & 1) * 2]);
                }
        }
    }

    // epilogue: gelu(gate) * up -> fp16 Ah
#pragma unroll
    for (int mt = 0; mt < 4; mt++)
#pragma unroll
        for (int nt = 0; nt < 4; nt++) {
            const float* cg = accG[mt][nt];
            const float* cu = accU[mt][nt];
            const int m = m0 + m0w + mt * 16 + (lane >> 2);
            const int n = n0 + n0w + nt * 8 + 2 * (lane & 3);
            __half2 h0 = __floats2half2_rn(gelu_tanh(cg[0]) * cu[0],
                                           gelu_tanh(cg[1]) * cu[1]);
            __half2 h1 = __floats2half2_rn(gelu_tanh(cg[2]) * cu[2],
                                           gelu_tanh(cg[3]) * cu[3]);
            *reinterpret_cast<__half2*>(g_Ah + ((size_t)e * T + m) * F + n)     = h0;
            *reinterpret_cast<__half2*>(g_Ah + ((size_t)e * T + m + 8) * F + n) = h1;
        }
}

// ---------------------------------------------------------------------------
// Kernel 2: out[T,H] = sum_e Ah[e] @ Dw[e]^T * (1/8)
//   grid (H/256, T/128), 8 warps = 2M x 4N, warp tile 64x64, K = E*F = 8192
// ---------------------------------------------------------------------------
constexpr int BN2 = 256;
constexpr uint32_t K2_SA = 0;
constexpr uint32_t K2_SB = BM * ROWB;               // 10240
constexpr uint32_t K2_STAGE = K2_SB + BN2 * ROWB;   // 30720
constexpr uint32_t K2_SMEM = ST * K2_STAGE;         // 122880

__global__ void __launch_bounds__(256, 1)
down_kernel(float* __restrict__ out) {
    extern __shared__ __align__(16) char smem[];
    const uint32_t sb = smem_u32(smem);
    const int tid = threadIdx.x, lane = tid & 31, wid = tid >> 5;
    const int n0 = blockIdx.x * BN2;
    const int m0 = blockIdx.y * BM;
    const int m0w = (wid & 1) * 64;
    const int n0w = (wid >> 1) * 64;

    const int r  = tid >> 2;
    const int c8 = (tid & 3) * 8;

    auto load_stage = [&](int s, int kt) {
        const uint32_t base = sb + (uint32_t)s * K2_STAGE;
        const int kk = kt * BK;
        const int e  = kk >> 10;      // F = 1024
        const int kf = kk & 1023;
        const __half* gA = g_Ah + ((size_t)e * T + m0) * F + kf;
        const __half* gB = g_Dh + ((size_t)e * H + n0) * F + kf;
        cp16(base + K2_SA + (uint32_t)r * ROWB + (tid & 3) * 16,
             gA + (size_t)r * F + c8);
        cp16(base + K2_SA + (uint32_t)(r + 64) * ROWB + (tid & 3) * 16,
             gA + (size_t)(r + 64) * F + c8);
#pragma unroll
        for (int rr = 0; rr < 4; rr++)
            cp16(base + K2_SB + (uint32_t)(r + rr * 64) * ROWB + (tid & 3) * 16,
                 gB + (size_t)(r + rr * 64) * F + c8);
    };

    constexpr int NK = (E * F) / BK;  // 256
    for (int s = 0; s < ST - 1; s++) { load_stage(s, s); cp_commit(); }

    float acc[4][8][4];
#pragma unroll
    for (int mt = 0; mt < 4; mt++)
#pragma unroll
        for (int nt = 0; nt < 8; nt++)
#pragma unroll
            for (int q = 0; q < 4; q++) acc[mt][nt][q] = 0.f;

#pragma unroll 1
    for (int kt = 0; kt < NK; kt++) {
        cp_wait<ST - 2>();
        __syncthreads();
        if (kt + ST - 1 < NK) { load_stage((kt + ST - 1) & (ST - 1), kt + ST - 1); cp_commit(); }

        const uint32_t stg = sb + (uint32_t)(kt & (ST - 1)) * K2_STAGE;
#pragma unroll
        for (int ks = 0; ks < 2; ks++) {
            uint32_t a[4][4], b[4][4];
#pragma unroll
            for (int mt = 0; mt < 4; mt++)
                ldm_x4(a[mt], stg + K2_SA + a_ldm_off(lane, m0w + mt * 16, ks));
#pragma unroll
            for (int nt2 = 0; nt2 < 4; nt2++)
                ldm_x4(b[nt2], stg + K2_SB + b_ldm_off(lane, n0w + nt2 * 16, ks));
#pragma unroll
            for (int mt = 0; mt < 4; mt++)
#pragma unroll
                for (int nt = 0; nt < 8; nt++)
                    mma16816(acc[mt][nt], a[mt], &b[nt >> 1][(nt & 1) * 2]);
        }
    }

    // epilogue: * 1/8, fp32 out
#pragma unroll
    for (int mt = 0; mt < 4; mt++)
#pragma unroll
        for (int nt = 0; nt < 8; nt++) {
            const float* cv = acc[mt][nt];
            const int m = m0 + m0w + mt * 16 + (lane >> 2);
            const int n = n0 + n0w + nt * 8 + 2 * (lane & 3);
            float2 v0 = make_float2(0.125f * cv[0], 0.125f * cv[1]);
            float2 v1 = make_float2(0.125f * cv[2], 0.125f * cv[3]);
            *reinterpret_cast<float2*>(out + (size_t)m * H + n)       = v0;
            *reinterpret_cast<float2*>(out + (size_t)(m + 8) * H + n) = v1;
        }
}

// ---------------------------------------------------------------------------
// fp32 -> fp16 conversion: one launch, blockIdx.y selects tensor
// ---------------------------------------------------------------------------
__global__ void cvt_kernel(const float4* __restrict__ s0, const float4* __restrict__ s1,
                           const float4* __restrict__ s2, const float4* __restrict__ s3,
                           uint2* __restrict__ d0, uint2* __restrict__ d1,
                           uint2* __restrict__ d2, uint2* __restrict__ d3, int n4) {
    const int i = blockIdx.x * blockDim.x + threadIdx.x;
    if (i >= n4) return;
    const float4* src;
    uint2* dst;
    switch (blockIdx.y) {
        case 0: src = s0; dst = d0; break;
        case 1: src = s1; dst = d1; break;
        case 2: src = s2; dst = d2; break;
        default: src = s3; dst = d3; break;
    }
    const float4 v = src[i];
    __half2 h0 = __floats2half2_rn(v.x, v.y);
    __half2 h1 = __floats2half2_rn(v.z, v.w);
    dst[i] = make_uint2(*reinterpret_cast<uint32_t*>(&h0),
                        *reinterpret_cast<uint32_t*>(&h1));
}

}  // namespace moe

// ---------------------------------------------------------------------------
// Host launcher
// ---------------------------------------------------------------------------
extern "C" void kernel_launch(void* const* d_in, const int* in_sizes, int n_in,
                              void* d_out, int out_size) {
    using namespace moe;
    const float* X  = (const float*)d_in[0];
    const float* Gw = (const float*)d_in[3];
    const float* Uw = (const float*)d_in[4];
    const float* Dw = (const float*)d_in[5];
    float* out = (float*)d_out;

    void *pXh, *pGh, *pUh, *pDh;
    cudaGetSymbolAddress(&pXh, g_Xh);
    cudaGetSymbolAddress(&pGh, g_Gh);
    cudaGetSymbolAddress(&pUh, g_Uh);
    cudaGetSymbolAddress(&pDh, g_Dh);

    const int n4 = (T * H) / 4;  // each operand tensor: 16,777,216 elements
    cvt_kernel<<<dim3(n4 / 256, 4), 256>>>(
        (const float4*)X, (const float4*)Gw, (const float4*)Uw, (const float4*)Dw,
        (uint2*)pXh, (uint2*)pGh, (uint2*)pUh, (uint2*)pDh, n4);

    cudaFuncSetAttribute(gate_up_kernel, cudaFuncAttributeMaxDynamicSharedMemorySize, K1_SMEM);
    cudaFuncSetAttribute(down_kernel,    cudaFuncAttributeMaxDynamicSharedMemorySize, K2_SMEM);

    gate_up_kernel<<<dim3(T / BM, F / BN1, E), 256, K1_SMEM>>>();
    down_kernel<<<dim3(H / BN2, T / BM), 256, K2_SMEM>>>(out);
}

// round 8
// speedup vs baseline: 1.3477x; 1.3477x over previous
#include <cuda_runtime.h>
#include <cuda_fp16.h>
#include <cstdint>

// ============================================================================
// MoE (uniform-routing Gemma4 experts):
//   out = sum_e gelu_tanh(X @ Gw[e]^T) * (X @ Uw[e]^T) @ Dw[e]^T * (1/E)
// T=8192 H=2048 F=1024 E=8.
// Portable sm_103 path: mma.sync.m16n8k16 + cp.async + ldmatrix.
// R8: R6 warp tiling (32x64, 2 CTAs/SM) + BK=64, ST=3 (half the syncs,
//     128B cp.async rows). 144B smem row stride, conflict-free ldmatrix.
// ============================================================================

namespace moe {

constexpr int T = 8192, H = 2048, F = 1024, E = 8;

__device__ __half g_Xh[(size_t)T * H];
__device__ __half g_Gh[(size_t)E * F * H];
__device__ __half g_Uh[(size_t)E * F * H];
__device__ __half g_Dh[(size_t)E * H * F];
__device__ __half g_Ah[(size_t)E * T * F];

#define DEVI __device__ __forceinline__

DEVI uint32_t smem_u32(const void* p) {
    uint32_t a;
    asm("{ .reg .u64 t; cvta.to.shared.u64 t, %1; cvt.u32.u64 %0, t; }"
        : "=r"(a) : "l"(p));
    return a;
}

DEVI void cp16(uint32_t dst, const void* src) {
    asm volatile("cp.async.cg.shared.global [%0], [%1], 16;"
                 :: "r"(dst), "l"(src) : "memory");
}
DEVI void cp_commit() { asm volatile("cp.async.commit_group;" ::: "memory"); }
template <int N>
DEVI void cp_wait() { asm volatile("cp.async.wait_group %0;" :: "n"(N) : "memory"); }

DEVI void ldm_x4(uint32_t* r, uint32_t addr) {
    asm volatile("ldmatrix.sync.aligned.m8n8.x4.shared.b16 {%0,%1,%2,%3}, [%4];"
                 : "=r"(r[0]), "=r"(r[1]), "=r"(r[2]), "=r"(r[3]) : "r"(addr));
}

DEVI void mma16816(float* d, const uint32_t* a, const uint32_t* b) {
    asm volatile(
        "mma.sync.aligned.m16n8k16.row.col.f32.f16.f16.f32 "
        "{%0,%1,%2,%3}, {%4,%5,%6,%7}, {%8,%9}, {%0,%1,%2,%3};"
        : "+f"(d[0]), "+f"(d[1]), "+f"(d[2]), "+f"(d[3])
        : "r"(a[0]), "r"(a[1]), "r"(a[2]), "r"(a[3]), "r"(b[0]), "r"(b[1]));
}

DEVI float gelu_tanh(float x) {
    return 0.5f * x * (1.0f + tanhf(0.7978845608028654f * x * (1.0f + 0.044715f * x * x)));
}

// ---- tiling constants ----
constexpr int BM = 128;        // M tile
constexpr int BK = 64;         // K chunk (halves) -> 128B rows
constexpr int ST = 3;          // pipeline stages
constexpr int LDS = 72;        // smem row stride in halves (144B): conflict-free
constexpr int ROWB = LDS * 2;  // 144

// ldmatrix byte offsets within a tile region (row-major rows x 64 halves, 144B stride)
DEVI uint32_t a_ldm_off(int lane, int m_row, int ks) {
    return ((uint32_t)(m_row + (lane & 15)) * LDS + ks * 16 + ((lane >> 4) << 3)) * 2;
}
DEVI uint32_t b_ldm_off(int lane, int n_row, int ks) {
    return ((uint32_t)(n_row + ((lane >> 4) << 3) + (lane & 7)) * LDS +
            ks * 16 + (((lane >> 3) & 1) << 3)) * 2;
}

// ---------------------------------------------------------------------------
// Kernel 1: gate & up GEMMs fused + gelu*mul -> g_Ah (fp16)
//   grid (T/128, F/64, E), 8 warps = 4M x 2N, warp tile 32x32 per GEMM (x2)
// ---------------------------------------------------------------------------
constexpr int BN1 = 64;
constexpr uint32_t K1_SA = 0;
constexpr uint32_t K1_SG = BM * ROWB;               // 18432
constexpr uint32_t K1_SU = K1_SG + BN1 * ROWB;      // 27648
constexpr uint32_t K1_STAGE = K1_SU + BN1 * ROWB;   // 36864
constexpr uint32_t K1_SMEM = ST * K1_STAGE;         // 110592

__global__ void __launch_bounds__(256, 2)
gate_up_kernel() {
    extern __shared__ __align__(16) char smem[];
    const uint32_t sb = smem_u32(smem);
    const int tid = threadIdx.x, lane = tid & 31, wid = tid >> 5;
    const int m0 = blockIdx.x * BM;
    const int n0 = blockIdx.y * BN1;
    const int e  = blockIdx.z;
    const int m0w = (wid & 3) * 32;   // 4 warps over M
    const int n0w = (wid >> 2) * 32;  // 2 warps over N

    const __half* gA = g_Xh + (size_t)m0 * H;
    const __half* gG = g_Gh + ((size_t)e * F + n0) * H;
    const __half* gU = g_Uh + ((size_t)e * F + n0) * H;

    const int r  = tid >> 3;       // 0..31 (row within 32-row group)
    const int c8 = (tid & 7) * 8;  // halves offset of 16B chunk (128B rows)

    auto load_stage = [&](int s, int kt) {
        const uint32_t base = sb + (uint32_t)s * K1_STAGE;
        const int k0 = kt * BK;
#pragma unroll
        for (int rr = 0; rr < 4; rr++)  // A: 128 rows
            cp16(base + K1_SA + (uint32_t)(r + rr * 32) * ROWB + (tid & 7) * 16,
                 gA + (size_t)(r + rr * 32) * H + k0 + c8);
#pragma unroll
        for (int rr = 0; rr < 2; rr++) {  // G, U: 64 rows each
            cp16(base + K1_SG + (uint32_t)(r + rr * 32) * ROWB + (tid & 7) * 16,
                 gG + (size_t)(r + rr * 32) * H + k0 + c8);
            cp16(base + K1_SU + (uint32_t)(r + rr * 32) * ROWB + (tid & 7) * 16,
                 gU + (size_t)(r + rr * 32) * H + k0 + c8);
        }
    };

    constexpr int NK = H / BK;  // 32
    for (int s = 0; s < ST - 1; s++) { load_stage(s, s); cp_commit(); }

    float accG[2][4][4], accU[2][4][4];
#pragma unroll
    for (int mt = 0; mt < 2; mt++)
#pragma unroll
        for (int nt = 0; nt < 4; nt++)
#pragma unroll
            for (int q = 0; q < 4; q++) { accG[mt][nt][q] = 0.f; accU[mt][nt][q] = 0.f; }

    int sc = 0, sl = ST - 1;  // compute stage, load stage
#pragma unroll 1
    for (int kt = 0; kt < NK; kt++) {
        cp_wait<ST - 2>();
        __syncthreads();
        if (kt + ST - 1 < NK) { load_stage(sl, kt + ST - 1); cp_commit(); }

        const uint32_t stg = sb + (uint32_t)sc * K1_STAGE;
#pragma unroll
        for (int ks = 0; ks < 4; ks++) {
            uint32_t a[2][4], bg[2][4], bu[2][4];
#pragma unroll
            for (int mt = 0; mt < 2; mt++)
                ldm_x4(a[mt], stg + K1_SA + a_ldm_off(lane, m0w + mt * 16, ks));
#pragma unroll
            for (int nt2 = 0; nt2 < 2; nt2++) {
                ldm_x4(bg[nt2], stg + K1_SG + b_ldm_off(lane, n0w + nt2 * 16, ks));
                ldm_x4(bu[nt2], stg + K1_SU + b_ldm_off(lane, n0w + nt2 * 16, ks));
            }
#pragma unroll
            for (int mt = 0; mt < 2; mt++)
#pragma unroll
                for (int nt = 0; nt < 4; nt++) {
                    mma16816(accG[mt][nt], a[mt], &bg[nt >> 1][(nt & 1) * 2]);
                    mma16816(accU[mt][nt], a[mt], &bu[nt >> 1][(nt & 1) * 2]);
                }
        }
        sc = (sc + 1 == ST) ? 0 : sc + 1;
        sl = (sl + 1 == ST) ? 0 : sl + 1;
    }

    // epilogue: gelu(gate) * up -> fp16 Ah
#pragma unroll
    for (int mt = 0; mt < 2; mt++)
#pragma unroll
        for (int nt = 0; nt < 4; nt++) {
            const float* cg = accG[mt][nt];
            const float* cu = accU[mt][nt];
            const int m = m0 + m0w + mt * 16 + (lane >> 2);
            const int n = n0 + n0w + nt * 8 + 2 * (lane & 3);
            __half2 h0 = __floats2half2_rn(gelu_tanh(cg[0]) * cu[0],
                                           gelu_tanh(cg[1]) * cu[1]);
            __half2 h1 = __floats2half2_rn(gelu_tanh(cg[2]) * cu[2],
                                           gelu_tanh(cg[3]) * cu[3]);
            *reinterpret_cast<__half2*>(g_Ah + ((size_t)e * T + m) * F + n)     = h0;
            *reinterpret_cast<__half2*>(g_Ah + ((size_t)e * T + m + 8) * F + n) = h1;
        }
}

// ---------------------------------------------------------------------------
// Kernel 2: out[T,H] = sum_e Ah[e] @ Dw[e]^T * (1/8)
//   grid (H/128, T/128), 8 warps = 4M x 2N, warp tile 32x64, K = E*F = 8192
// ---------------------------------------------------------------------------
constexpr int BN2 = 128;
constexpr uint32_t K2_SA = 0;
constexpr uint32_t K2_SB = BM * ROWB;               // 18432
constexpr uint32_t K2_STAGE = K2_SB + BN2 * ROWB;   // 36864
constexpr uint32_t K2_SMEM = ST * K2_STAGE;         // 110592

__global__ void __launch_bounds__(256, 2)
down_kernel(float* __restrict__ out) {
    extern __shared__ __align__(16) char smem[];
    const uint32_t sb = smem_u32(smem);
    const int tid = threadIdx.x, lane = tid & 31, wid = tid >> 5;
    const int n0 = blockIdx.x * BN2;
    const int m0 = blockIdx.y * BM;
    const int m0w = (wid & 3) * 32;
    const int n0w = (wid >> 2) * 64;

    const int r  = tid >> 3;
    const int c8 = (tid & 7) * 8;

    auto load_stage = [&](int s, int kt) {
        const uint32_t base = sb + (uint32_t)s * K2_STAGE;
        const int kk = kt * BK;
        const int e  = kk >> 10;      // F = 1024
        const int kf = kk & 1023;
        const __half* gA = g_Ah + ((size_t)e * T + m0) * F + kf;
        const __half* gB = g_Dh + ((size_t)e * H + n0) * F + kf;
#pragma unroll
        for (int rr = 0; rr < 4; rr++) {
            cp16(base + K2_SA + (uint32_t)(r + rr * 32) * ROWB + (tid & 7) * 16,
                 gA + (size_t)(r + rr * 32) * F + c8);
            cp16(base + K2_SB + (uint32_t)(r + rr * 32) * ROWB + (tid & 7) * 16,
                 gB + (size_t)(r + rr * 32) * F + c8);
        }
    };

    constexpr int NK = (E * F) / BK;  // 128
    for (int s = 0; s < ST - 1; s++) { load_stage(s, s); cp_commit(); }

    float acc[2][8][4];
#pragma unroll
    for (int mt = 0; mt < 2; mt++)
#pragma unroll
        for (int nt = 0; nt < 8; nt++)
#pragma unroll
            for (int q = 0; q < 4; q++) acc[mt][nt][q] = 0.f;

    int sc = 0, sl = ST - 1;
#pragma unroll 1
    for (int kt = 0; kt < NK; kt++) {
        cp_wait<ST - 2>();
        __syncthreads();
        if (kt + ST - 1 < NK) { load_stage(sl, kt + ST - 1); cp_commit(); }

        const uint32_t stg = sb + (uint32_t)sc * K2_STAGE;
#pragma unroll
        for (int ks = 0; ks < 4; ks++) {
            uint32_t a[2][4], b[4][4];
#pragma unroll
            for (int mt = 0; mt < 2; mt++)
                ldm_x4(a[mt], stg + K2_SA + a_ldm_off(lane, m0w + mt * 16, ks));
#pragma unroll
            for (int nt2 = 0; nt2 < 4; nt2++)
                ldm_x4(b[nt2], stg + K2_SB + b_ldm_off(lane, n0w + nt2 * 16, ks));
#pragma unroll
            for (int mt = 0; mt < 2; mt++)
#pragma unroll
                for (int nt = 0; nt < 8; nt++)
                    mma16816(acc[mt][nt], a[mt], &b[nt >> 1][(nt & 1) * 2]);
        }
        sc = (sc + 1 == ST) ? 0 : sc + 1;
        sl = (sl + 1 == ST) ? 0 : sl + 1;
    }

    // epilogue: * 1/8, fp32 out
#pragma unroll
    for (int mt = 0; mt < 2; mt++)
#pragma unroll
        for (int nt = 0; nt < 8; nt++) {
            const float* cv = acc[mt][nt];
            const int m = m0 + m0w + mt * 16 + (lane >> 2);
            const int n = n0 + n0w + nt * 8 + 2 * (lane & 3);
            float2 v0 = make_float2(0.125f * cv[0], 0.125f * cv[1]);
            float2 v1 = make_float2(0.125f * cv[2], 0.125f * cv[3]);
            *reinterpret_cast<float2*>(out + (size_t)m * H + n)       = v0;
            *reinterpret_cast<float2*>(out + (size_t)(m + 8) * H + n) = v1;
        }
}

// ---------------------------------------------------------------------------
// fp32 -> fp16 conversion: one launch, blockIdx.y selects tensor
// ---------------------------------------------------------------------------
__global__ void cvt_kernel(const float4* __restrict__ s0, const float4* __restrict__ s1,
                           const float4* __restrict__ s2, const float4* __restrict__ s3,
                           uint2* __restrict__ d0, uint2* __restrict__ d1,
                           uint2* __restrict__ d2, uint2* __restrict__ d3, int n4) {
    const int i = blockIdx.x * blockDim.x + threadIdx.x;
    if (i >= n4) return;
    const float4* src;
    uint2* dst;
    switch (blockIdx.y) {
        case 0: src = s0; dst = d0; break;
        case 1: src = s1; dst = d1; break;
        case 2: src = s2; dst = d2; break;
        default: src = s3; dst = d3; break;
    }
    const float4 v = src[i];
    __half2 h0 = __floats2half2_rn(v.x, v.y);
    __half2 h1 = __floats2half2_rn(v.z, v.w);
    dst[i] = make_uint2(*reinterpret_cast<uint32_t*>(&h0),
                        *reinterpret_cast<uint32_t*>(&h1));
}

}  // namespace moe

// ---------------------------------------------------------------------------
// Host launcher
// ---------------------------------------------------------------------------
extern "C" void kernel_launch(void* const* d_in, const int* in_sizes, int n_in,
                              void* d_out, int out_size) {
    using namespace moe;
    const float* X  = (const float*)d_in[0];
    const float* Gw = (const float*)d_in[3];
    const float* Uw = (const float*)d_in[4];
    const float* Dw = (const float*)d_in[5];
    float* out = (float*)d_out;

    void *pXh, *pGh, *pUh, *pDh;
    cudaGetSymbolAddress(&pXh, g_Xh);
    cudaGetSymbolAddress(&pGh, g_Gh);
    cudaGetSymbolAddress(&pUh, g_Uh);
    cudaGetSymbolAddress(&pDh, g_Dh);

    const int n4 = (T * H) / 4;  // each operand tensor: 16,777,216 elements
    cvt_kernel<<<dim3(n4 / 256, 4), 256>>>(
        (const float4*)X, (const float4*)Gw, (const float4*)Uw, (const float4*)Dw,
        (uint2*)pXh, (uint2*)pGh, (uint2*)pUh, (uint2*)pDh, n4);

    cudaFuncSetAttribute(gate_up_kernel, cudaFuncAttributeMaxDynamicSharedMemorySize, K1_SMEM);
    cudaFuncSetAttribute(down_kernel,    cudaFuncAttributeMaxDynamicSharedMemorySize, K2_SMEM);

    gate_up_kernel<<<dim3(T / BM, F / BN1, E), 256, K1_SMEM>>>();
    down_kernel<<<dim3(H / BN2, T / BM), 256, K2_SMEM>>>(out);
}